// round 16
// baseline (speedup 1.0000x reference)
#include <cuda_runtime.h>
#include <math.h>
#include <stdint.h>

#define N_PTS 12288
#define DIM   128
#define BI    32
#define BJ    48
#define TILES (N_PTS / BJ)   /* 256 */
#define EPSF  1e-7f
#define MAXN  (1.0f - 1e-3f)

// Scratch (device globals — no allocation allowed)
__device__ float  g_xt[N_PTS * DIM];   // logmap0(x), pre-rounded to tf32
__device__ float4 g_rw[N_PTS];         // per-row: (E1=e^wh1, F1=e^{0.2wh1}, Ethr=e^{-wh1}, 0)
__device__ __align__(16) float2 g_ef[N_PTS];  // per-col: (e2=e^wh2, f2=e^{0.2wh2})

__device__ __forceinline__ unsigned f2tf32(float f) {
    unsigned u;
    asm("cvt.rna.tf32.f32 %0, %1;" : "=r"(u) : "f"(f));
    return u;
}

// m16n8k8 tf32 MMA, fp32 accumulate
#define MMA_TF32(d, a0, a1, a2, a3, b0, b1)                                   \
    asm volatile(                                                             \
        "mma.sync.aligned.m16n8k8.row.col.f32.tf32.tf32.f32 "                 \
        "{%0,%1,%2,%3}, {%4,%5,%6,%7}, {%8,%9}, {%0,%1,%2,%3};"               \
        : "+f"(d[0]), "+f"(d[1]), "+f"(d[2]), "+f"(d[3])                      \
        : "r"(a0), "r"(a1), "r"(a2), "r"(a3), "r"(b0), "r"(b1))

#define CP16(dst, src) \
    asm volatile("cp.async.cg.shared.global [%0], [%1], 16;" :: "r"(dst), "l"(src))
#define CPA_MBAR(a) \
    asm volatile("cp.async.mbarrier.arrive.noinc.shared.b64 [%0];" :: "r"(a) : "memory")
#define MB_INIT(a, c) \
    asm volatile("mbarrier.init.shared.b64 [%0], %1;" :: "r"(a), "r"((unsigned)(c)) : "memory")
#define MB_ARRIVE(a) \
    asm volatile("mbarrier.arrive.shared.b64 _, [%0];" :: "r"(a) : "memory")
#define MB_WAIT(a, ph) do {                                                        \
    asm volatile("{\n\t.reg .pred P1;\n\tWL%=:\n\t"                                \
        "mbarrier.try_wait.parity.acquire.cta.shared::cta.b64 P1, [%0], %1, 0x989680;\n\t" \
        "@P1 bra.uni WD%=;\n\tbra.uni WL%=;\n\tWD%=:\n\t}"                         \
        :: "r"(a), "r"((unsigned)(ph)) : "memory");                                \
} while (0)

// ---------------------------------------------------------------------------
// Kernel 1: logmap0 + wh projections; factored exp terms; xt tf32-rounded
// ---------------------------------------------------------------------------
__global__ void prep_kernel(const float* __restrict__ x, const float* __restrict__ a) {
    int i = blockIdx.x;
    int d = threadIdx.x;
    float xv = x[(size_t)i * DIM + d];
    float s0 = xv * xv, s1 = xv * a[d], s2 = xv * a[DIM + d];
#pragma unroll
    for (int o = 16; o > 0; o >>= 1) {
        s0 += __shfl_down_sync(0xffffffffu, s0, o);
        s1 += __shfl_down_sync(0xffffffffu, s1, o);
        s2 += __shfl_down_sync(0xffffffffu, s2, o);
    }
    __shared__ float sm0[4], sm1[4], sm2[4];
    __shared__ float sscale;
    int w = d >> 5, l = d & 31;
    if (l == 0) { sm0[w] = s0; sm1[w] = s1; sm2[w] = s2; }
    __syncthreads();
    if (d == 0) {
        float t0 = sm0[0] + sm0[1] + sm0[2] + sm0[3];
        float t1 = sm1[0] + sm1[1] + sm1[2] + sm1[3];
        float t2 = sm2[0] + sm2[1] + sm2[2] + sm2[3];
        float n  = sqrtf(t0);
        float nc = fminf(fmaxf(n, EPSF), 1.0f - EPSF);
        float sc = atanhf(nc) / nc;
        sscale   = sc;
        float wh1 = sc * t1, wh2 = sc * t2;
        g_rw[i] = make_float4(expf(wh1), expf(0.2f * wh1), expf(-wh1), 0.f);
        g_ef[i] = make_float2(expf(wh2), expf(0.2f * wh2));
    }
    __syncthreads();
    g_xt[(size_t)i * DIM + d] = __uint_as_float(f2tf32(xv * sscale));
}

// ---------------------------------------------------------------------------
// Kernel 2: warp-specialized fused masked attention.
// Warps 0-3 producers: adj LDG -> P (tf32) -> pT ring; xt cp.async + mbar arrive.
// Warps 4-7 consumers: mma.sync engines, mbarrier-gated. No syncthreads in loop.
// 2-stage ring; mbar parity: use n = t/2, stage s = t&1.
// ---------------------------------------------------------------------------
__global__ __launch_bounds__(256, 3) void attn_kernel(const int* __restrict__ adj,
                                                      float* __restrict__ out) {
    __shared__ __align__(16) float xt_s[2][BJ][132];  // 50.7 KB, tf32, j-permuted rows
    __shared__ __align__(16) float pTs[2][BI][56];    // 14.3 KB, tf32, j-permuted cols
    __shared__ float l_s[BI];
    __shared__ __align__(8) unsigned long long mbar[6]; // fpt0 fpt1 fxt0 fxt1 emp0 emp1

    const int tid  = threadIdx.x;
    const int i0   = blockIdx.x * BI;
    const int lane = tid & 31, w = tid >> 5;
    const uint32_t mbb = (uint32_t)__cvta_generic_to_shared(&mbar[0]);
    const uint32_t FPT = mbb, FXT = mbb + 16, EMP = mbb + 32;

    if (tid == 0) {
        MB_INIT(FPT, 128); MB_INIT(FPT + 8, 128);   // producer threads
        MB_INIT(FXT, 128); MB_INIT(FXT + 8, 128);   // producer cp.async arrivals
        MB_INIT(EMP, 128); MB_INIT(EMP + 8, 128);   // consumer threads
    }
    __syncthreads();

    if (w < 4) {
        // =================== PRODUCER ===================
        const int p_row = tid >> 2;          // 0..31
        const int p_jo  = tid & 3;           // 0..3 -> js [12*p_jo, 12*p_jo+12)
        const float4 rw = g_rw[i0 + p_row];
        const float E1 = rw.x, F1 = rw.y, Ethr = rw.z;
        const int j0loc = 12 * p_jo;
        const int4* adjr4 = (const int4*)(adj + (size_t)(i0 + p_row) * N_PTS + j0loc);
        const float4* efr4 = (const float4*)(g_ef + j0loc);

        int pcol[12];
#pragma unroll
        for (int k = 0; k < 12; k++) {
            int jj = j0loc + k;
            pcol[k] = ((jj >> 3) << 3) + ((jj & 3) << 1) + ((jj & 7) >> 2);
        }

        // xt cp.async offsets: 12 chunks per producer thread
        unsigned xtb[2];
        xtb[0] = (unsigned)__cvta_generic_to_shared(&xt_s[0][0][0]);
        xtb[1] = (unsigned)__cvta_generic_to_shared(&xt_s[1][0][0]);
        unsigned xdoff[12]; int xsoff[12];
#pragma unroll
        for (int s = 0; s < 12; s++) {
            int slot = tid + (s << 7);
            int jn = slot >> 5;
            int c4 = (slot & 31) << 2;
            int r7 = jn & 7;
            int lr = (jn & ~7) + ((r7 & 3) << 1) + (r7 >> 2);
            xdoff[s] = (unsigned)((lr * 132 + c4) << 2);
            xsoff[s] = jn * DIM + c4;
        }

        // prefetch tile 0 operands
        int4   av[3];
        float4 ev[6];
#pragma unroll
        for (int c = 0; c < 3; c++) av[c] = __ldg(adjr4 + c);
#pragma unroll
        for (int c = 0; c < 6; c++) ev[c] = __ldg(efr4 + c);

        float lsum = 0.f;

        for (int t = 0; t < TILES; t++) {
            const int s = t & 1, n = t >> 1;

            MB_WAIT(EMP + 8 * s, (n + 1) & 1);   // stage free (passes at t=0,1)

            // issue xt(t) copy into stage s + completion arrive
            {
                const float* srcb = g_xt + (size_t)t * BJ * DIM;
#pragma unroll
                for (int c = 0; c < 12; c++) CP16(xtb[s] + xdoff[c], srcb + xsoff[c]);
                CPA_MBAR(FXT + 8 * s);
            }

            // compute P(t) from prefetched regs; store tf32 into pT stage s
            {
                float* ps = &pTs[s][p_row][0];
                const int* am = (const int*)av;
                const float* ef = (const float*)ev;
#pragma unroll
                for (int k = 0; k < 12; k++) {
                    float e2 = ef[2 * k], f2 = ef[2 * k + 1];
                    float p = (am[k] > 0) ? ((e2 >= Ethr) ? E1 * e2 : F1 * f2) : 0.f;
                    p = __uint_as_float(f2tf32(p));
                    ps[pcol[k]] = p;
                    lsum += p;
                }
            }
            MB_ARRIVE(FPT + 8 * s);

            // prefetch operands for t+1
            if (t + 1 < TILES) {
                const int4*   an = adjr4 + (size_t)(t + 1) * (BJ / 4);
                const float4* en = efr4 + (size_t)(t + 1) * (BJ / 2);
#pragma unroll
                for (int c = 0; c < 3; c++) av[c] = __ldg(an + c);
#pragma unroll
                for (int c = 0; c < 6; c++) ev[c] = __ldg(en + c);
            }
        }

        // l reduction: 4 lanes per row (consecutive)
        lsum += __shfl_xor_sync(0xffffffffu, lsum, 1);
        lsum += __shfl_xor_sync(0xffffffffu, lsum, 2);
        if ((tid & 3) == 0) l_s[p_row] = lsum;

    } else {
        // =================== CONSUMER ===================
        const int g = lane >> 2, tig = lane & 3;
        const int wc = w - 4;                 // 0..3 -> col slice
        const int sl = wc << 5;
        const int colb = sl + (g << 2);

        float acc[2][4][4];                   // [m-tile][nt][c]
#pragma unroll
        for (int mt = 0; mt < 2; mt++)
#pragma unroll
            for (int nt = 0; nt < 4; nt++)
#pragma unroll
                for (int c = 0; c < 4; c++) acc[mt][nt][c] = 0.f;

        for (int t = 0; t < TILES; t++) {
            const int s = t & 1, n = t >> 1;
            MB_WAIT(FPT + 8 * s, n & 1);
            MB_WAIT(FXT + 8 * s, n & 1);

            const float (*xs)[132] = xt_s[s];
            const float (*pp)[56]  = pTs[s];
#pragma unroll
            for (int s6 = 0; s6 < 6; s6++) {
                int lr = (s6 << 3) + (tig << 1);
                float2 pa0 = *(const float2*)&pp[g][lr];        // m-tile 0
                float2 pa1 = *(const float2*)&pp[8 + g][lr];
                float2 pb0 = *(const float2*)&pp[16 + g][lr];   // m-tile 1
                float2 pb1 = *(const float2*)&pp[24 + g][lr];
                uint4  xb0 = *(const uint4*)&xs[lr][colb];
                uint4  xb1 = *(const uint4*)&xs[lr + 1][colb];
                unsigned a0 = __float_as_uint(pa0.x), a1 = __float_as_uint(pa1.x);
                unsigned a2 = __float_as_uint(pa0.y), a3 = __float_as_uint(pa1.y);
                unsigned b0 = __float_as_uint(pb0.x), b1 = __float_as_uint(pb1.x);
                unsigned b2 = __float_as_uint(pb0.y), b3 = __float_as_uint(pb1.y);
                MMA_TF32(acc[0][0], a0, a1, a2, a3, xb0.x, xb1.x);
                MMA_TF32(acc[0][1], a0, a1, a2, a3, xb0.y, xb1.y);
                MMA_TF32(acc[0][2], a0, a1, a2, a3, xb0.z, xb1.z);
                MMA_TF32(acc[0][3], a0, a1, a2, a3, xb0.w, xb1.w);
                MMA_TF32(acc[1][0], b0, b1, b2, b3, xb0.x, xb1.x);
                MMA_TF32(acc[1][1], b0, b1, b2, b3, xb0.y, xb1.y);
                MMA_TF32(acc[1][2], b0, b1, b2, b3, xb0.z, xb1.z);
                MMA_TF32(acc[1][3], b0, b1, b2, b3, xb0.w, xb1.w);
            }
            MB_ARRIVE(EMP + 8 * s);
        }

        // stash acc in registers until after the barrier below, then scatter
        __syncthreads();   // join producers; all mma/pT use complete
#pragma unroll
        for (int mt = 0; mt < 2; mt++) {
            int m0 = mt << 4;
#pragma unroll
            for (int nt = 0; nt < 4; nt++) {
                xt_s[0][m0 + g][sl + (tig << 3) + nt]         = acc[mt][nt][0];
                xt_s[0][m0 + g][sl + (tig << 3) + 4 + nt]     = acc[mt][nt][1];
                xt_s[0][m0 + 8 + g][sl + (tig << 3) + nt]     = acc[mt][nt][2];
                xt_s[0][m0 + 8 + g][sl + (tig << 3) + 4 + nt] = acc[mt][nt][3];
            }
        }
    }

    // producers hit the same barrier as consumers' pre-scatter sync
    if (w < 4) __syncthreads();

    __syncthreads();   // scatter + l_s visible to all

    // ---- epilogue (all 8 warps): v = acc/l; expmap0; proj ----
    {
        int cx = lane;
#pragma unroll
        for (int r = 0; r < 4; r++) {
            int row = (w << 2) + r;
            float linv = 1.f / l_s[row];
            float4 v = *(const float4*)&xt_s[0][row][cx << 2];
            float v0 = v.x * linv, v1 = v.y * linv;
            float v2 = v.z * linv, v3 = v.w * linv;
            float part = v0 * v0 + v1 * v1 + v2 * v2 + v3 * v3;
#pragma unroll
            for (int o2 = 16; o2 > 0; o2 >>= 1)
                part += __shfl_xor_sync(0xffffffffu, part, o2);
            float n  = sqrtf(part);
            float nc = fmaxf(n, EPSF);
            float sc = tanhf(nc) / nc;            // expmap0 scale
            float ny = fmaxf(sc * n, EPSF);       // ||y||
            float f  = (ny > MAXN) ? sc * (MAXN / ny) : sc;  // proj
            *(float4*)&out[(size_t)(i0 + row) * DIM + (cx << 2)] =
                make_float4(v0 * f, v1 * f, v2 * f, v3 * f);
        }
    }
}

// ---------------------------------------------------------------------------
extern "C" void kernel_launch(void* const* d_in, const int* in_sizes, int n_in,
                              void* d_out, int out_size) {
    const float* x = nullptr;
    const int*   adj = nullptr;
    const float* a = nullptr;
    for (int i = 0; i < n_in; i++) {
        if (in_sizes[i] == N_PTS * DIM)      x   = (const float*)d_in[i];
        else if (in_sizes[i] == 2 * DIM)     a   = (const float*)d_in[i];
        else                                 adj = (const int*)d_in[i];
    }
    float* out = (float*)d_out;

    prep_kernel<<<N_PTS, DIM>>>(x, a);
    attn_kernel<<<N_PTS / BI, 256>>>(adj, out);
}

// round 17
// speedup vs baseline: 1.4684x; 1.4684x over previous
#include <cuda_runtime.h>
#include <cuda_fp16.h>
#include <math.h>
#include <stdint.h>

#define N_PTS 12288
#define DIM   128
#define BI    32
#define BJ    64
#define TILES (N_PTS / BJ)   /* 192 */
#define EPSF  1e-7f
#define MAXN  (1.0f - 1e-3f)

// ---- dynamic smem arena offsets (bytes) ----
#define XT_OFF   0                      /* 3 stages x 128 rows x 144 B */
#define XT_STAGE (128 * 144)            /* 18432 */
#define PT_OFF   (3 * XT_STAGE)         /* 55296 */
#define PT_STAGE (32 * 144)             /* 4608  */
#define SMEM_DYN (PT_OFF + 2 * PT_STAGE) /* 64512 */

// Scratch (device globals — no allocation allowed)
__device__ float  g_xt[N_PTS * DIM];    // logmap0(x) fp32 (feeds transpose)
__device__ float4 g_rw[N_PTS];          // (E1=e^wh1, F1=e^{0.2wh1}, Ethr=e^{-wh1}, 0)
__device__ __align__(16) float2 g_ef[N_PTS];   // (e2=e^wh2, f2=e^{0.2wh2})
__device__ __half g_xh[(size_t)DIM * N_PTS];   // xt^T as half, [d][j]

// fp16 m16n8k16 MMA, fp32 accumulate
#define MMA_F16(d, a0, a1, a2, a3, b0, b1)                                    \
    asm volatile(                                                             \
        "mma.sync.aligned.m16n8k16.row.col.f32.f16.f16.f32 "                  \
        "{%0,%1,%2,%3}, {%4,%5,%6,%7}, {%8,%9}, {%0,%1,%2,%3};"               \
        : "+f"(d[0]), "+f"(d[1]), "+f"(d[2]), "+f"(d[3])                      \
        : "r"(a0), "r"(a1), "r"(a2), "r"(a3), "r"(b0), "r"(b1))

#define CP16(dst, src) \
    asm volatile("cp.async.cg.shared.global [%0], [%1], 16;" :: "r"(dst), "l"(src))
#define CP_COMMIT() asm volatile("cp.async.commit_group;")
#define CP_WAIT1()  asm volatile("cp.async.wait_group 1;" ::: "memory")

// ---------------------------------------------------------------------------
// Kernel 1: logmap0 + wh projections; factored exp terms; xt fp32
// ---------------------------------------------------------------------------
__global__ void prep_kernel(const float* __restrict__ x, const float* __restrict__ a) {
    int i = blockIdx.x;
    int d = threadIdx.x;
    float xv = x[(size_t)i * DIM + d];
    float s0 = xv * xv, s1 = xv * a[d], s2 = xv * a[DIM + d];
#pragma unroll
    for (int o = 16; o > 0; o >>= 1) {
        s0 += __shfl_down_sync(0xffffffffu, s0, o);
        s1 += __shfl_down_sync(0xffffffffu, s1, o);
        s2 += __shfl_down_sync(0xffffffffu, s2, o);
    }
    __shared__ float sm0[4], sm1[4], sm2[4];
    __shared__ float sscale;
    int w = d >> 5, l = d & 31;
    if (l == 0) { sm0[w] = s0; sm1[w] = s1; sm2[w] = s2; }
    __syncthreads();
    if (d == 0) {
        float t0 = sm0[0] + sm0[1] + sm0[2] + sm0[3];
        float t1 = sm1[0] + sm1[1] + sm1[2] + sm1[3];
        float t2 = sm2[0] + sm2[1] + sm2[2] + sm2[3];
        float n  = sqrtf(t0);
        float nc = fminf(fmaxf(n, EPSF), 1.0f - EPSF);
        float sc = atanhf(nc) / nc;
        sscale   = sc;
        float wh1 = sc * t1, wh2 = sc * t2;
        g_rw[i] = make_float4(expf(wh1), expf(0.2f * wh1), expf(-wh1), 0.f);
        g_ef[i] = make_float2(expf(wh2), expf(0.2f * wh2));
    }
    __syncthreads();
    g_xt[(size_t)i * DIM + d] = xv * sscale;
}

// ---------------------------------------------------------------------------
// Kernel 1b: transpose xt [j][d] fp32 -> half plane [d][j]
// ---------------------------------------------------------------------------
__global__ void tr_kernel() {
    __shared__ float ts[32][33];
    int i0 = blockIdx.x * 32, d0 = blockIdx.y * 32;
    int tx = threadIdx.x, ty = threadIdx.y;
#pragma unroll
    for (int yy = ty; yy < 32; yy += 8)
        ts[yy][tx] = g_xt[(size_t)(i0 + yy) * DIM + d0 + tx];
    __syncthreads();
#pragma unroll
    for (int yy = ty; yy < 32; yy += 8)
        g_xh[(size_t)(d0 + yy) * N_PTS + i0 + tx] = __float2half_rn(ts[tx][yy]);
}

// ---------------------------------------------------------------------------
// Kernel 2: fused masked attention, fp16 m16n8k16 mma, 1 sync/tile.
// Per tile: p(t)[regs only] -> wait_group 1 -> sync -> issue xt(t+2) ->
//           LDG adj/ef(t+1) -> mma(t).
// Warp w: m-tile (w&1)*16, n-slice (w>>1)*32. Thread (g=lane>>2, tig=lane&3).
// Fragments: A = P[m][j] natural half layout; B = xt^T[d][j] half layout.
// 144B row stride => bank 4g+tig, conflict-free.
// ---------------------------------------------------------------------------
__global__ void __launch_bounds__(256, 3) attn_kernel(const int* __restrict__ adj,
                                                      float* __restrict__ out) {
    extern __shared__ __align__(16) char arena[];
    __shared__ float l_s[BI];

    const int tid  = threadIdx.x;
    const int i0   = blockIdx.x * BI;
    const int lane = tid & 31, w = tid >> 5;
    const int g    = lane >> 2, tig = lane & 3;
    const int m0   = (w & 1) << 4;
    const int sl   = (w >> 1) << 5;
    const int p_row = tid >> 3, p_jo = tid & 7;   // 8 js per thread: j0=8*p_jo

    float acc[4][4];
#pragma unroll
    for (int nt = 0; nt < 4; nt++)
#pragma unroll
        for (int c = 0; c < 4; c++) acc[nt][c] = 0.f;

    // cp.async offsets: 4 x 16B chunks per thread per xt tile (128 rows x 128B)
    const unsigned smb = (unsigned)__cvta_generic_to_shared(arena);
    unsigned xdoff[4];
    const char* xsrc[4];
#pragma unroll
    for (int s = 0; s < 4; s++) {
        int slot = tid + (s << 8);
        int d = slot >> 3, c = slot & 7;
        xdoff[s] = (unsigned)(XT_OFF + d * 144 + c * 16);
        xsrc[s]  = (const char*)g_xh + ((size_t)d * N_PTS) * 2 + c * 16;
    }

    const float4 rw = g_rw[i0 + p_row];
    const float E1 = rw.x, F1 = rw.y, Ethr = rw.z;
    const int4* adjr = (const int4*)(adj + (size_t)(i0 + p_row) * N_PTS + 8 * p_jo);
    const float4* efr = (const float4*)(g_ef + 8 * p_jo);

    // ---- prologue: issue xt(0), xt(1); LDG adj/ef(0) ----
#pragma unroll
    for (int s = 0; s < 4; s++) CP16(smb + xdoff[s], xsrc[s]);
    CP_COMMIT();
#pragma unroll
    for (int s = 0; s < 4; s++) CP16(smb + XT_STAGE + xdoff[s], xsrc[s] + 128);
    CP_COMMIT();
    int4   av0 = __ldg(adjr), av1 = __ldg(adjr + 1);
    float4 ef0 = __ldg(efr), ef1 = __ldg(efr + 1);
    float4 ef2 = __ldg(efr + 2), ef3 = __ldg(efr + 3);

    float lsum = 0.f;

    for (int t = 0; t < TILES; t++) {
        const int b2 = t & 1, s3 = t % 3;

        // ---- p-compute(t): registers only; store half P ----
        {
            float p0 = (av0.x > 0) ? ((ef0.x >= Ethr) ? E1 * ef0.x : F1 * ef0.y) : 0.f;
            float p1 = (av0.y > 0) ? ((ef0.z >= Ethr) ? E1 * ef0.z : F1 * ef0.w) : 0.f;
            float p2 = (av0.z > 0) ? ((ef1.x >= Ethr) ? E1 * ef1.x : F1 * ef1.y) : 0.f;
            float p3 = (av0.w > 0) ? ((ef1.z >= Ethr) ? E1 * ef1.z : F1 * ef1.w) : 0.f;
            float p4 = (av1.x > 0) ? ((ef2.x >= Ethr) ? E1 * ef2.x : F1 * ef2.y) : 0.f;
            float p5 = (av1.y > 0) ? ((ef2.z >= Ethr) ? E1 * ef2.z : F1 * ef2.w) : 0.f;
            float p6 = (av1.z > 0) ? ((ef3.x >= Ethr) ? E1 * ef3.x : F1 * ef3.y) : 0.f;
            float p7 = (av1.w > 0) ? ((ef3.z >= Ethr) ? E1 * ef3.z : F1 * ef3.w) : 0.f;
            lsum += ((p0 + p1) + (p2 + p3)) + ((p4 + p5) + (p6 + p7));
            __half2 h01 = __floats2half2_rn(p0, p1);
            __half2 h23 = __floats2half2_rn(p2, p3);
            __half2 h45 = __floats2half2_rn(p4, p5);
            __half2 h67 = __floats2half2_rn(p6, p7);
            uint4 st = make_uint4(*(unsigned*)&h01, *(unsigned*)&h23,
                                  *(unsigned*)&h45, *(unsigned*)&h67);
            *(uint4*)(arena + PT_OFF + b2 * PT_STAGE + p_row * 144 + p_jo * 16) = st;
        }

        CP_WAIT1();         // xt(t) resident (xt(t+1) may still fly)
        __syncthreads();    // xt(t) + pT(t) visible to all; stage (t+2)%3 free

        // ---- issue xt(t+2); LDG adj/ef(t+1) (covered by mma) ----
        if (t + 2 < TILES) {
            const unsigned base = smb + ((t + 2) % 3) * XT_STAGE;
            const int off = (t + 2) * 128;  // bytes: 64 halves per tile
#pragma unroll
            for (int s = 0; s < 4; s++) CP16(base + xdoff[s], xsrc[s] + off);
        }
        CP_COMMIT();
        if (t + 1 < TILES) {
            const int4*   an = adjr + (size_t)(t + 1) * (BJ / 4);
            const float4* en = efr + (size_t)(t + 1) * (BJ / 2);
            av0 = __ldg(an); av1 = __ldg(an + 1);
            ef0 = __ldg(en); ef1 = __ldg(en + 1);
            ef2 = __ldg(en + 2); ef3 = __ldg(en + 3);
        }

        // ---- mma(t): 16 fp16 m16n8k16 per warp ----
        {
            const char* pA0 = arena + PT_OFF + b2 * PT_STAGE + (m0 + g) * 144 + 4 * tig;
            const char* pA1 = pA0 + 8 * 144;
            const char* pB  = arena + XT_OFF + s3 * XT_STAGE + (sl + g) * 144 + 4 * tig;
#pragma unroll
            for (int ks = 0; ks < 4; ks++) {
                unsigned a0 = *(const unsigned*)(pA0 + 32 * ks);
                unsigned a2 = *(const unsigned*)(pA0 + 32 * ks + 16);
                unsigned a1 = *(const unsigned*)(pA1 + 32 * ks);
                unsigned a3 = *(const unsigned*)(pA1 + 32 * ks + 16);
#pragma unroll
                for (int nt = 0; nt < 4; nt++) {
                    unsigned b0 = *(const unsigned*)(pB + nt * (8 * 144) + 32 * ks);
                    unsigned b1 = *(const unsigned*)(pB + nt * (8 * 144) + 32 * ks + 16);
                    MMA_F16(acc[nt], a0, a1, a2, a3, b0, b1);
                }
            }
        }
    }

    // ---- finalize l (8 lanes per row) ----
    lsum += __shfl_xor_sync(0xffffffffu, lsum, 1);
    lsum += __shfl_xor_sync(0xffffffffu, lsum, 2);
    lsum += __shfl_xor_sync(0xffffffffu, lsum, 4);
    if ((lane & 7) == 0) l_s[p_row] = lsum;
    __syncthreads();

    // ---- scatter accumulators into arena (rows stride 132 floats) ----
    float* stg = (float*)arena;
#pragma unroll
    for (int nt = 0; nt < 4; nt++) {
        int cb = sl + 8 * nt + 2 * tig;
        stg[(m0 + g) * 132 + cb]         = acc[nt][0];
        stg[(m0 + g) * 132 + cb + 1]     = acc[nt][1];
        stg[(m0 + 8 + g) * 132 + cb]     = acc[nt][2];
        stg[(m0 + 8 + g) * 132 + cb + 1] = acc[nt][3];
    }
    __syncthreads();

    // ---- epilogue: v = acc/l; expmap0; proj ----
    {
        int cx = lane;
#pragma unroll
        for (int r = 0; r < 4; r++) {
            int row = (w << 2) + r;
            float linv = 1.f / l_s[row];
            float4 v = *(const float4*)&stg[row * 132 + (cx << 2)];
            float v0 = v.x * linv, v1 = v.y * linv;
            float v2 = v.z * linv, v3 = v.w * linv;
            float part = v0 * v0 + v1 * v1 + v2 * v2 + v3 * v3;
#pragma unroll
            for (int o2 = 16; o2 > 0; o2 >>= 1)
                part += __shfl_xor_sync(0xffffffffu, part, o2);
            float n  = sqrtf(part);
            float nc = fmaxf(n, EPSF);
            float sc = tanhf(nc) / nc;            // expmap0 scale
            float ny = fmaxf(sc * n, EPSF);       // ||y||
            float f  = (ny > MAXN) ? sc * (MAXN / ny) : sc;  // proj
            *(float4*)&out[(size_t)(i0 + row) * DIM + (cx << 2)] =
                make_float4(v0 * f, v1 * f, v2 * f, v3 * f);
        }
    }
}

// ---------------------------------------------------------------------------
extern "C" void kernel_launch(void* const* d_in, const int* in_sizes, int n_in,
                              void* d_out, int out_size) {
    const float* x = nullptr;
    const int*   adj = nullptr;
    const float* a = nullptr;
    for (int i = 0; i < n_in; i++) {
        if (in_sizes[i] == N_PTS * DIM)      x   = (const float*)d_in[i];
        else if (in_sizes[i] == 2 * DIM)     a   = (const float*)d_in[i];
        else                                 adj = (const int*)d_in[i];
    }
    float* out = (float*)d_out;

    static int attr_set = 0;
    if (!attr_set) {
        cudaFuncSetAttribute(attn_kernel, cudaFuncAttributeMaxDynamicSharedMemorySize,
                             SMEM_DYN);
        attr_set = 1;
    }

    prep_kernel<<<N_PTS, DIM>>>(x, a);
    tr_kernel<<<dim3(N_PTS / 32, DIM / 32), dim3(32, 8)>>>();
    attn_kernel<<<N_PTS / BI, 256, SMEM_DYN>>>(adj, out);
}